// round 10
// baseline (speedup 1.0000x reference)
#include <cuda_runtime.h>

#define N_NODES  100000
#define N_EDGES  3200000
#define N_GRAPHS 128

// ---------------- scratch (static device globals; no runtime alloc) ----------
__device__ int   g_cnt[N_NODES];
__device__ int   g_rowptr[N_NODES];            // after k_fill: END of each row
__device__ int   g_bsums[128];
__device__ int   g_done;                       // pool->head ticket (zeroed each launch)
__device__ float g_dinv[N_NODES];
__device__ int   g_csr[N_EDGES];               // src only (features pre-scaled by dinv)
__device__ __align__(16) unsigned g_xs[N_NODES * 8];    // x*dinv as bf16 pairs
__device__ __align__(16) unsigned g_aggu[N_NODES * 32]; // aggregation output (bf16 pairs)
__device__ __align__(16) unsigned g_ha[N_NODES * 32];   // activations bf16 (L1 scaled, L3 raw)
__device__ __align__(16) unsigned g_hb[N_NODES * 32];   // activations bf16 (L2 scaled)
__device__ __align__(16) float g_pool[N_GRAPHS * 64];

// bf16 pair decode: EXACT (bf16 is fp32 with truncated mantissa). 1 instr each.
__device__ __forceinline__ float bf_lo(unsigned v) { return __int_as_float(v << 16); }
__device__ __forceinline__ float bf_hi(unsigned v) { return __int_as_float(v & 0xffff0000u); }
// pack two floats into a bf16 pair (lo = first/even column), single instruction
__device__ __forceinline__ unsigned bf2_pack(float lo, float hi) {
    unsigned r;
    asm("cvt.rn.bf16x2.f32 %0, %1, %2;" : "=r"(r) : "f"(hi), "f"(lo));
    return r;
}

// ---------------- degree histogram ----------------
__global__ void k_zero_cnt() {
    int i = blockIdx.x * blockDim.x + threadIdx.x;
    if (i < N_NODES) g_cnt[i] = 0;
    if (i == 0) g_done = 0;
}

__global__ void k_hist(const int4* __restrict__ dst4) {
    int i = blockIdx.x * blockDim.x + threadIdx.x;   // N_EDGES/4 threads
    int4 d = __ldg(&dst4[i]);
    atomicAdd(&g_cnt[d.x], 1);
    atomicAdd(&g_cnt[d.y], 1);
    atomicAdd(&g_cnt[d.z], 1);
    atomicAdd(&g_cnt[d.w], 1);
}

// ---------------- exclusive scan over 100k counts (2 kernels) ----------------
__global__ void k_scan_blocks() {
    __shared__ int s[1024];
    int tid = threadIdx.x;
    int i = blockIdx.x * 1024 + tid;
    int v = (i < N_NODES) ? g_cnt[i] : 0;
    s[tid] = v;
    __syncthreads();
    for (int off = 1; off < 1024; off <<= 1) {
        int t = (tid >= off) ? s[tid - off] : 0;
        __syncthreads();
        s[tid] += t;
        __syncthreads();
    }
    if (i < N_NODES) g_rowptr[i] = s[tid] - v;   // exclusive within block
    if (tid == 1023) g_bsums[blockIdx.x] = s[1023];
}

// scan finish + dinv + pre-scaled bf16 x (fused)
__global__ void k_scan_add(const float* __restrict__ x) {
    __shared__ int s_pre;
    int tid = threadIdx.x;
    if (tid < 32) {
        int acc = 0;
        for (int b = tid; b < blockIdx.x; b += 32) acc += g_bsums[b];
        for (int off = 16; off > 0; off >>= 1) acc += __shfl_xor_sync(0xffffffffu, acc, off);
        if (tid == 0) s_pre = acc;
    }
    __syncthreads();
    int i = blockIdx.x * 1024 + tid;
    if (i < N_NODES) {
        g_rowptr[i] += s_pre;
        float dv = rsqrtf((float)(g_cnt[i] + 1));   // +1 self loop
        g_dinv[i] = dv;
        const float4* xr = (const float4*)(x + (size_t)i * 16);
        uint4* xo = (uint4*)(g_xs + (size_t)i * 8);
#pragma unroll
        for (int c = 0; c < 2; c++) {
            float4 v0 = __ldg(&xr[2 * c]);
            float4 v1 = __ldg(&xr[2 * c + 1]);
            uint4 u;
            u.x = bf2_pack(v0.x * dv, v0.y * dv);
            u.y = bf2_pack(v0.z * dv, v0.w * dv);
            u.z = bf2_pack(v1.x * dv, v1.y * dv);
            u.w = bf2_pack(v1.z * dv, v1.w * dv);
            xo[c] = u;
        }
    }
}

// ---------------- CSR fill: rowptr itself is the cursor (becomes row END) ----
__global__ void k_fill(const int4* __restrict__ src4, const int4* __restrict__ dst4) {
    int i = blockIdx.x * blockDim.x + threadIdx.x;   // N_EDGES/4 threads
    int4 s = __ldg(&src4[i]);
    int4 d = __ldg(&dst4[i]);
    g_csr[atomicAdd(&g_rowptr[d.x], 1)] = s.x;
    g_csr[atomicAdd(&g_rowptr[d.y], 1)] = s.y;
    g_csr[atomicAdd(&g_rowptr[d.z], 1)] = s.z;
    g_csr[atomicAdd(&g_rowptr[d.w], 1)] = s.w;
}

// ---------------- layer 1 fused: agg(xs,16) then @W1[16,64]+b1, relu --------
// warp per node; 4 subs of 8 lanes, sub handles every-4th edge; lane = col pair.
// writes g_ha PRE-SCALED by dinv[w] for layer-2 consumption.
__global__ void k_agg16_mm1(const float* __restrict__ W1, const float* __restrict__ b1) {
    __shared__ float2 sW[16 * 32];
    __shared__ float2 sB[32];
    int tid = threadIdx.x;
    for (int idx = tid; idx < 16 * 32; idx += 256) sW[idx] = __ldg((const float2*)W1 + idx);
    if (tid < 32) sB[tid] = __ldg((const float2*)b1 + tid);
    __syncthreads();

    int w = (blockIdx.x * 256 + tid) >> 5;
    if (w >= N_NODES) return;
    int lane = tid & 31;
    int sub = lane >> 3, c2 = lane & 7;     // c2 covers cols {2c2, 2c2+1}
    int e1 = __ldg(&g_rowptr[w]);
    int e0 = e1 - __ldg(&g_cnt[w]);
    float2 a = make_float2(0.f, 0.f);
    float dv = g_dinv[w];
    if (sub == 0) {                          // self loop (xs already dinv-scaled)
        unsigned u = __ldg(&g_xs[(size_t)w * 8 + c2]);
        a.x = bf_lo(u); a.y = bf_hi(u);
    }
    int k = e0 + sub;
    for (; k + 12 < e1; k += 16) {           // 4 edges per sub in flight (16/warp)
        int s0 = __ldg(&g_csr[k]);
        int s1 = __ldg(&g_csr[k + 4]);
        int s2 = __ldg(&g_csr[k + 8]);
        int s3 = __ldg(&g_csr[k + 12]);
        unsigned u0 = __ldg(&g_xs[(size_t)s0 * 8 + c2]);
        unsigned u1 = __ldg(&g_xs[(size_t)s1 * 8 + c2]);
        unsigned u2 = __ldg(&g_xs[(size_t)s2 * 8 + c2]);
        unsigned u3 = __ldg(&g_xs[(size_t)s3 * 8 + c2]);
        a.x += bf_lo(u0); a.y += bf_hi(u0);
        a.x += bf_lo(u1); a.y += bf_hi(u1);
        a.x += bf_lo(u2); a.y += bf_hi(u2);
        a.x += bf_lo(u3); a.y += bf_hi(u3);
    }
    for (; k < e1; k += 4) {
        unsigned u = __ldg(&g_xs[(size_t)__ldg(&g_csr[k]) * 8 + c2]);
        a.x += bf_lo(u); a.y += bf_hi(u);
    }
    a.x *= dv; a.y *= dv;                    // dinv[dst]
    // combine 4 subs
    a.x += __shfl_xor_sync(0xffffffffu, a.x, 8);
    a.y += __shfl_xor_sync(0xffffffffu, a.y, 8);
    a.x += __shfl_xor_sync(0xffffffffu, a.x, 16);
    a.y += __shfl_xor_sync(0xffffffffu, a.y, 16);
    // lane j (j<8) holds agg cols {2j, 2j+1}; replicated in all lanes

    // mm 16 -> 64: lane computes cols {2*lane, 2*lane+1}
    float2 acc = sB[lane];
#pragma unroll
    for (int kk = 0; kk < 16; kk++) {
        float ak = __shfl_sync(0xffffffffu, (kk & 1) ? a.y : a.x, kk >> 1);
        float2 wv = sW[kk * 32 + lane];
        acc.x = fmaf(ak, wv.x, acc.x);
        acc.y = fmaf(ak, wv.y, acc.y);
    }
    // pre-scale by dinv[w] for next layer's aggregation
    g_ha[(size_t)w * 32 + lane] = bf2_pack(fmaxf(acc.x, 0.f) * dv, fmaxf(acc.y, 0.f) * dv);
}

// ---------------- 64-wide aggregation over pre-scaled bf16 -> g_aggu ---------
// warp per node; 4 subs of 8 lanes; sub handles every-4th edge; lane loads a
// uint4 (8 bf16 cols). One feature LDG warp-instruction covers 4 edges.
template <int SRC>
__global__ void k_agg64() {
    const unsigned* __restrict__ h = (SRC == 0) ? g_ha : g_hb;
    int w = (blockIdx.x * 256 + threadIdx.x) >> 5;
    if (w >= N_NODES) return;
    int lane = threadIdx.x & 31;
    int sub = lane >> 3, t = lane & 7;       // t covers cols {8t..8t+7}
    int e1 = __ldg(&g_rowptr[w]);
    int e0 = e1 - __ldg(&g_cnt[w]);
    float dv = g_dinv[w];

    float4 accA = make_float4(0.f, 0.f, 0.f, 0.f);   // cols 8t..8t+3
    float4 accB = make_float4(0.f, 0.f, 0.f, 0.f);   // cols 8t+4..8t+7
    if (sub == 0) {                          // self loop
        uint4 sv = __ldg((const uint4*)(h + (size_t)w * 32) + t);
        accA.x = bf_lo(sv.x); accA.y = bf_hi(sv.x);
        accA.z = bf_lo(sv.y); accA.w = bf_hi(sv.y);
        accB.x = bf_lo(sv.z); accB.y = bf_hi(sv.z);
        accB.z = bf_lo(sv.w); accB.w = bf_hi(sv.w);
    }

    int k = e0 + sub;
    for (; k + 12 < e1; k += 16) {           // 4 edges per sub in flight (16/warp)
        int s0 = __ldg(&g_csr[k]);
        int s1 = __ldg(&g_csr[k + 4]);
        int s2 = __ldg(&g_csr[k + 8]);
        int s3 = __ldg(&g_csr[k + 12]);
        uint4 f0 = __ldg((const uint4*)(h + (size_t)s0 * 32) + t);
        uint4 f1 = __ldg((const uint4*)(h + (size_t)s1 * 32) + t);
        uint4 f2 = __ldg((const uint4*)(h + (size_t)s2 * 32) + t);
        uint4 f3 = __ldg((const uint4*)(h + (size_t)s3 * 32) + t);
        accA.x += bf_lo(f0.x); accA.y += bf_hi(f0.x);
        accA.z += bf_lo(f0.y); accA.w += bf_hi(f0.y);
        accB.x += bf_lo(f0.z); accB.y += bf_hi(f0.z);
        accB.z += bf_lo(f0.w); accB.w += bf_hi(f0.w);
        accA.x += bf_lo(f1.x); accA.y += bf_hi(f1.x);
        accA.z += bf_lo(f1.y); accA.w += bf_hi(f1.y);
        accB.x += bf_lo(f1.z); accB.y += bf_hi(f1.z);
        accB.z += bf_lo(f1.w); accB.w += bf_hi(f1.w);
        accA.x += bf_lo(f2.x); accA.y += bf_hi(f2.x);
        accA.z += bf_lo(f2.y); accA.w += bf_hi(f2.y);
        accB.x += bf_lo(f2.z); accB.y += bf_hi(f2.z);
        accB.z += bf_lo(f2.w); accB.w += bf_hi(f2.w);
        accA.x += bf_lo(f3.x); accA.y += bf_hi(f3.x);
        accA.z += bf_lo(f3.y); accA.w += bf_hi(f3.y);
        accB.x += bf_lo(f3.z); accB.y += bf_hi(f3.z);
        accB.z += bf_lo(f3.w); accB.w += bf_hi(f3.w);
    }
    for (; k < e1; k += 4) {
        int s = __ldg(&g_csr[k]);
        uint4 f = __ldg((const uint4*)(h + (size_t)s * 32) + t);
        accA.x += bf_lo(f.x); accA.y += bf_hi(f.x);
        accA.z += bf_lo(f.y); accA.w += bf_hi(f.y);
        accB.x += bf_lo(f.z); accB.y += bf_hi(f.z);
        accB.z += bf_lo(f.w); accB.w += bf_hi(f.w);
    }
    // dinv[dst], then combine the 4 subs (xor 8, 16)
    accA.x *= dv; accA.y *= dv; accA.z *= dv; accA.w *= dv;
    accB.x *= dv; accB.y *= dv; accB.z *= dv; accB.w *= dv;
#pragma unroll
    for (int off = 8; off <= 16; off <<= 1) {
        accA.x += __shfl_xor_sync(0xffffffffu, accA.x, off);
        accA.y += __shfl_xor_sync(0xffffffffu, accA.y, off);
        accA.z += __shfl_xor_sync(0xffffffffu, accA.z, off);
        accA.w += __shfl_xor_sync(0xffffffffu, accA.w, off);
        accB.x += __shfl_xor_sync(0xffffffffu, accB.x, off);
        accB.y += __shfl_xor_sync(0xffffffffu, accB.y, off);
        accB.z += __shfl_xor_sync(0xffffffffu, accB.z, off);
        accB.w += __shfl_xor_sync(0xffffffffu, accB.w, off);
    }
    if (sub == 0) {
        uint4 st;
        st.x = bf2_pack(accA.x, accA.y);
        st.y = bf2_pack(accA.z, accA.w);
        st.z = bf2_pack(accB.x, accB.y);
        st.w = bf2_pack(accB.z, accB.w);
        ((uint4*)(g_aggu + (size_t)w * 32))[t] = st;
    }
}

// ---------------- matmul 64x64 + bias + relu: g_aggu (bf16) -> bf16 buffer ---
// SCALE=1: multiply rows by dinv[row] on output (feeds another aggregation).
template <int DST, int SCALE>
__global__ void k_mm64(const float* __restrict__ Wm, const float* __restrict__ bv) {
    unsigned* __restrict__ out = (DST == 0) ? g_ha : g_hb;
    __shared__ float4 sIn[64 * 16];
    __shared__ float sDv[64];
    int tid = threadIdx.x;           // 256
    int row0 = blockIdx.x * 64;
    int col = tid & 63;
    float wreg[64];
#pragma unroll
    for (int k = 0; k < 64; k++) wreg[k] = __ldg(&Wm[k * 64 + col]);
    float bias = __ldg(&bv[col]);
    int nrows = min(64, N_NODES - row0);
    for (int idx = tid; idx < nrows * 16; idx += 256) {
        uint2 v = __ldg((const uint2*)(g_aggu + (size_t)row0 * 32) + idx);
        sIn[idx] = make_float4(bf_lo(v.x), bf_hi(v.x), bf_lo(v.y), bf_hi(v.y));
    }
    if (SCALE && tid < nrows) sDv[tid] = g_dinv[row0 + tid];
    __syncthreads();
    int rg = tid >> 6;
    for (int r = rg; r < nrows; r += 4) {
        float acc = bias;
#pragma unroll
        for (int k4 = 0; k4 < 16; k4++) {
            float4 v = sIn[r * 16 + k4];
            acc = fmaf(v.x, wreg[4 * k4 + 0], acc);
            acc = fmaf(v.y, wreg[4 * k4 + 1], acc);
            acc = fmaf(v.z, wreg[4 * k4 + 2], acc);
            acc = fmaf(v.w, wreg[4 * k4 + 3], acc);
        }
        acc = fmaxf(acc, 0.f);
        if (SCALE) acc *= sDv[r];
        // pair with neighbor column and store one bf16x2 per even thread
        float nxt = __shfl_down_sync(0xffffffffu, acc, 1);
        if ((tid & 1) == 0)
            out[(size_t)(row0 + r) * 32 + (col >> 1)] = bf2_pack(acc, nxt);
    }
}

// ---------------- fused mean pool + MLP head (last block does the head) ------
__global__ void k_pool_head(const int* __restrict__ batch,
                            const float* __restrict__ Wf1, const float* __restrict__ bf1,
                            const float* __restrict__ Wf2, const float* __restrict__ bf2,
                            float* __restrict__ out) {
    int g = blockIdx.x;
    int lo = 0, hi = N_NODES;
    while (lo < hi) { int mid = (lo + hi) >> 1; if (__ldg(&batch[mid]) < g) lo = mid + 1; else hi = mid; }
    int start = lo;
    lo = start; hi = N_NODES;
    while (lo < hi) { int mid = (lo + hi) >> 1; if (__ldg(&batch[mid]) < g + 1) lo = mid + 1; else hi = mid; }
    int end = lo;

    __shared__ float2 sp[8][32];
    int cp = threadIdx.x & 31, rg = threadIdx.x >> 5;
    float2 acc = make_float2(0.f, 0.f);
    for (int r = start + rg; r < end; r += 8) {
        unsigned u = __ldg(&g_ha[(size_t)r * 32 + cp]);
        acc.x += bf_lo(u); acc.y += bf_hi(u);
    }
    sp[rg][cp] = acc;
    __syncthreads();
    if (rg == 0) {
        float2 t = sp[0][cp];
#pragma unroll
        for (int i = 1; i < 8; i++) { t.x += sp[i][cp].x; t.y += sp[i][cp].y; }
        float cnt = (float)(end - start);
        if (cnt < 1.f) cnt = 1.f;
        ((float2*)g_pool)[g * 32 + cp] = make_float2(t.x / cnt, t.y / cnt);
    }

    // last block to finish runs the head
    __shared__ int s_last;
    __threadfence();
    __syncthreads();
    if (threadIdx.x == 0) s_last = (atomicAdd(&g_done, 1) == N_GRAPHS - 1);
    __syncthreads();
    if (!s_last) return;
    __threadfence();

    int gg = threadIdx.x;
    if (gg >= N_GRAPHS) return;
    float p[64];
#pragma unroll
    for (int k = 0; k < 64; k++) p[k] = g_pool[gg * 64 + k];
    float o = __ldg(&bf2[0]);
#pragma unroll 4
    for (int j = 0; j < 32; j++) {
        float hj = __ldg(&bf1[j]);
#pragma unroll
        for (int k = 0; k < 64; k++) hj = fmaf(p[k], __ldg(&Wf1[k * 32 + j]), hj);
        o = fmaf(fmaxf(hj, 0.f), __ldg(&Wf2[j]), o);
    }
    out[gg] = o;
}

// ---------------- launch ----------------
extern "C" void kernel_launch(void* const* d_in, const int* in_sizes, int n_in,
                              void* d_out, int out_size) {
    const float* x   = (const float*)d_in[0];
    const int*   ei  = (const int*)d_in[1];
    const int4*  src4 = (const int4*)ei;
    const int4*  dst4 = (const int4*)(ei + N_EDGES);
    const int*   batch = (const int*)d_in[3];
    const float* W1 = (const float*)d_in[4];  const float* b1 = (const float*)d_in[5];
    const float* W2 = (const float*)d_in[6];  const float* b2 = (const float*)d_in[7];
    const float* W3 = (const float*)d_in[8];  const float* b3 = (const float*)d_in[9];
    const float* Wf1 = (const float*)d_in[10]; const float* bf1 = (const float*)d_in[11];
    const float* Wf2 = (const float*)d_in[12]; const float* bf2 = (const float*)d_in[13];
    float* out = (float*)d_out;

    const int nb_scan = (N_NODES + 1023) / 1024;       // 98
    const int eb4 = (N_EDGES / 4) / 256;               // 3125
    const int wb = (N_NODES * 32 + 255) / 256;         // one warp per node: 12500
    const int mb = (N_NODES + 63) / 64;                // 1563

    k_zero_cnt<<<(N_NODES + 255) / 256, 256>>>();
    k_hist<<<eb4, 256>>>(dst4);
    k_scan_blocks<<<nb_scan, 1024>>>();
    k_scan_add<<<nb_scan, 1024>>>(x);
    k_fill<<<eb4, 256>>>(src4, dst4);

    k_agg16_mm1<<<wb, 256>>>(W1, b1);          // layer 1 fused -> ha (scaled)
    k_agg64<0><<<wb, 256>>>();                 // gather ha -> aggu
    k_mm64<1, 1><<<mb, 256>>>(W2, b2);         // aggu@W2 -> hb (scaled)
    k_agg64<1><<<wb, 256>>>();                 // gather hb -> aggu
    k_mm64<0, 0><<<mb, 256>>>(W3, b3);         // aggu@W3 -> ha (raw, for pool)

    k_pool_head<<<N_GRAPHS, 256>>>(batch, Wf1, bf1, Wf2, bf2, out);
}

// round 12
// speedup vs baseline: 1.0218x; 1.0218x over previous
#include <cuda_runtime.h>

#define N_NODES  100000
#define N_EDGES  3200000
#define N_GRAPHS 128

// ---------------- scratch (static device globals; no runtime alloc) ----------
__device__ int   g_cnt[N_NODES];
__device__ int   g_rowptr[N_NODES];            // exclusive row start (never mutated)
__device__ int   g_bsums[128];
__device__ int   g_done;                       // pool->head ticket (zeroed each launch)
__device__ float g_dinv[N_NODES];
__device__ __align__(16) int g_rank[N_EDGES];  // within-node rank of each edge
__device__ int   g_csr[N_EDGES];               // src only (features pre-scaled by dinv)
__device__ __align__(16) unsigned g_xs[N_NODES * 8];    // x*dinv as bf16 pairs
__device__ __align__(16) unsigned g_aggu[N_NODES * 32]; // aggregation output (bf16 pairs)
__device__ __align__(16) unsigned g_ha[N_NODES * 32];   // activations bf16 (L1 scaled, L3 raw)
__device__ __align__(16) unsigned g_hb[N_NODES * 32];   // activations bf16 (L2 scaled)
__device__ __align__(16) float g_pool[N_GRAPHS * 64];

// bf16 pair decode: EXACT (bf16 is fp32 with truncated mantissa). 1 instr each.
__device__ __forceinline__ float bf_lo(unsigned v) { return __int_as_float(v << 16); }
__device__ __forceinline__ float bf_hi(unsigned v) { return __int_as_float(v & 0xffff0000u); }
// pack two floats into a bf16 pair (lo = first/even column), single instruction
__device__ __forceinline__ unsigned bf2_pack(float lo, float hi) {
    unsigned r;
    asm("cvt.rn.bf16x2.f32 %0, %1, %2;" : "=r"(r) : "f"(hi), "f"(lo));
    return r;
}

// ---------------- degree histogram ----------------
__global__ void k_zero_cnt() {
    int i = blockIdx.x * blockDim.x + threadIdx.x;
    if (i < N_NODES) g_cnt[i] = 0;
    if (i == 0) g_done = 0;
}

// histogram + per-edge rank (atomicAdd return value is a free unique rank)
__global__ void k_hist(const int4* __restrict__ dst4) {
    int i = blockIdx.x * blockDim.x + threadIdx.x;   // N_EDGES/4 threads
    int4 d = __ldg(&dst4[i]);
    int4 r;
    r.x = atomicAdd(&g_cnt[d.x], 1);
    r.y = atomicAdd(&g_cnt[d.y], 1);
    r.z = atomicAdd(&g_cnt[d.z], 1);
    r.w = atomicAdd(&g_cnt[d.w], 1);
    ((int4*)g_rank)[i] = r;
}

// ---------------- exclusive scan over 100k counts (2 kernels) ----------------
__global__ void k_scan_blocks() {
    __shared__ int s[1024];
    int tid = threadIdx.x;
    int i = blockIdx.x * 1024 + tid;
    int v = (i < N_NODES) ? g_cnt[i] : 0;
    s[tid] = v;
    __syncthreads();
    for (int off = 1; off < 1024; off <<= 1) {
        int t = (tid >= off) ? s[tid - off] : 0;
        __syncthreads();
        s[tid] += t;
        __syncthreads();
    }
    if (i < N_NODES) g_rowptr[i] = s[tid] - v;   // exclusive within block
    if (tid == 1023) g_bsums[blockIdx.x] = s[1023];
}

// scan finish + dinv + pre-scaled bf16 x (fused)
__global__ void k_scan_add(const float* __restrict__ x) {
    __shared__ int s_pre;
    int tid = threadIdx.x;
    if (tid < 32) {
        int acc = 0;
        for (int b = tid; b < blockIdx.x; b += 32) acc += g_bsums[b];
        for (int off = 16; off > 0; off >>= 1) acc += __shfl_xor_sync(0xffffffffu, acc, off);
        if (tid == 0) s_pre = acc;
    }
    __syncthreads();
    int i = blockIdx.x * 1024 + tid;
    if (i < N_NODES) {
        g_rowptr[i] += s_pre;
        float dv = rsqrtf((float)(g_cnt[i] + 1));   // +1 self loop
        g_dinv[i] = dv;
        const float4* xr = (const float4*)(x + (size_t)i * 16);
        uint4* xo = (uint4*)(g_xs + (size_t)i * 8);
#pragma unroll
        for (int c = 0; c < 2; c++) {
            float4 v0 = __ldg(&xr[2 * c]);
            float4 v1 = __ldg(&xr[2 * c + 1]);
            uint4 u;
            u.x = bf2_pack(v0.x * dv, v0.y * dv);
            u.y = bf2_pack(v0.z * dv, v0.w * dv);
            u.z = bf2_pack(v1.x * dv, v1.y * dv);
            u.w = bf2_pack(v1.z * dv, v1.w * dv);
            xo[c] = u;
        }
    }
}

// ---------------- CSR fill: ATOMIC-FREE (pos = rowptr[d] + rank[e]) ----------
__global__ void k_fill(const int4* __restrict__ src4, const int4* __restrict__ dst4) {
    int i = blockIdx.x * blockDim.x + threadIdx.x;   // N_EDGES/4 threads
    int4 s = __ldg(&src4[i]);
    int4 d = __ldg(&dst4[i]);
    int4 r = __ldg((const int4*)g_rank + i);
    int p0 = __ldg(&g_rowptr[d.x]) + r.x;
    int p1 = __ldg(&g_rowptr[d.y]) + r.y;
    int p2 = __ldg(&g_rowptr[d.z]) + r.z;
    int p3 = __ldg(&g_rowptr[d.w]) + r.w;
    g_csr[p0] = s.x;
    g_csr[p1] = s.y;
    g_csr[p2] = s.z;
    g_csr[p3] = s.w;
}

// ---------------- layer 1 fused: agg(xs,16) then @W1[16,64]+b1, relu --------
// warp per node; 4 subs of 8 lanes, sub handles every-4th edge; lane = col pair.
// writes g_ha PRE-SCALED by dinv[w] for layer-2 consumption.
__global__ void k_agg16_mm1(const float* __restrict__ W1, const float* __restrict__ b1) {
    __shared__ float2 sW[16 * 32];
    __shared__ float2 sB[32];
    int tid = threadIdx.x;
    for (int idx = tid; idx < 16 * 32; idx += 256) sW[idx] = __ldg((const float2*)W1 + idx);
    if (tid < 32) sB[tid] = __ldg((const float2*)b1 + tid);
    __syncthreads();

    int w = (blockIdx.x * 256 + tid) >> 5;
    if (w >= N_NODES) return;
    int lane = tid & 31;
    int sub = lane >> 3, c2 = lane & 7;     // c2 covers cols {2c2, 2c2+1}
    int e0 = __ldg(&g_rowptr[w]);
    int e1 = e0 + __ldg(&g_cnt[w]);
    float2 a = make_float2(0.f, 0.f);
    float dv = g_dinv[w];
    if (sub == 0) {                          // self loop (xs already dinv-scaled)
        unsigned u = __ldg(&g_xs[(size_t)w * 8 + c2]);
        a.x = bf_lo(u); a.y = bf_hi(u);
    }
    int k = e0 + sub;
    for (; k + 12 < e1; k += 16) {           // 4 edges per sub in flight (16/warp)
        int s0 = __ldg(&g_csr[k]);
        int s1 = __ldg(&g_csr[k + 4]);
        int s2 = __ldg(&g_csr[k + 8]);
        int s3 = __ldg(&g_csr[k + 12]);
        unsigned u0 = __ldg(&g_xs[(size_t)s0 * 8 + c2]);
        unsigned u1 = __ldg(&g_xs[(size_t)s1 * 8 + c2]);
        unsigned u2 = __ldg(&g_xs[(size_t)s2 * 8 + c2]);
        unsigned u3 = __ldg(&g_xs[(size_t)s3 * 8 + c2]);
        a.x += bf_lo(u0); a.y += bf_hi(u0);
        a.x += bf_lo(u1); a.y += bf_hi(u1);
        a.x += bf_lo(u2); a.y += bf_hi(u2);
        a.x += bf_lo(u3); a.y += bf_hi(u3);
    }
    for (; k < e1; k += 4) {
        unsigned u = __ldg(&g_xs[(size_t)__ldg(&g_csr[k]) * 8 + c2]);
        a.x += bf_lo(u); a.y += bf_hi(u);
    }
    a.x *= dv; a.y *= dv;                    // dinv[dst]
    // combine 4 subs
    a.x += __shfl_xor_sync(0xffffffffu, a.x, 8);
    a.y += __shfl_xor_sync(0xffffffffu, a.y, 8);
    a.x += __shfl_xor_sync(0xffffffffu, a.x, 16);
    a.y += __shfl_xor_sync(0xffffffffu, a.y, 16);
    // lane j (j<8) holds agg cols {2j, 2j+1}; replicated in all lanes

    // mm 16 -> 64: lane computes cols {2*lane, 2*lane+1}
    float2 acc = sB[lane];
#pragma unroll
    for (int kk = 0; kk < 16; kk++) {
        float ak = __shfl_sync(0xffffffffu, (kk & 1) ? a.y : a.x, kk >> 1);
        float2 wv = sW[kk * 32 + lane];
        acc.x = fmaf(ak, wv.x, acc.x);
        acc.y = fmaf(ak, wv.y, acc.y);
    }
    // pre-scale by dinv[w] for next layer's aggregation
    g_ha[(size_t)w * 32 + lane] = bf2_pack(fmaxf(acc.x, 0.f) * dv, fmaxf(acc.y, 0.f) * dv);
}

// ---------------- 64-wide aggregation over pre-scaled bf16 -> g_aggu ---------
// (R9 proven shape: 2 subs x 16 lanes x uint2, 8 edges per sub in flight)
template <int SRC>
__global__ void k_agg64() {
    const unsigned* __restrict__ h = (SRC == 0) ? g_ha : g_hb;
    int w = (blockIdx.x * 256 + threadIdx.x) >> 5;
    if (w >= N_NODES) return;
    int lane = threadIdx.x & 31;
    int sub = lane >> 4, t = lane & 15;      // t covers cols {4t..4t+3}
    int e0 = __ldg(&g_rowptr[w]);
    int e1 = e0 + __ldg(&g_cnt[w]);
    float dv = g_dinv[w];

    float4 acc = make_float4(0.f, 0.f, 0.f, 0.f);
    if (sub == 0) {                          // self loop
        uint2 sv = __ldg((const uint2*)(h + (size_t)w * 32) + t);
        acc.x = bf_lo(sv.x); acc.y = bf_hi(sv.x);
        acc.z = bf_lo(sv.y); acc.w = bf_hi(sv.y);
    }

    int k = e0 + sub;
    for (; k + 14 < e1; k += 16) {           // 8 edges per sub in flight
        int s0 = __ldg(&g_csr[k]);
        int s1 = __ldg(&g_csr[k + 2]);
        int s2 = __ldg(&g_csr[k + 4]);
        int s3 = __ldg(&g_csr[k + 6]);
        int s4 = __ldg(&g_csr[k + 8]);
        int s5 = __ldg(&g_csr[k + 10]);
        int s6 = __ldg(&g_csr[k + 12]);
        int s7 = __ldg(&g_csr[k + 14]);
        uint2 f0 = __ldg((const uint2*)(h + (size_t)s0 * 32) + t);
        uint2 f1 = __ldg((const uint2*)(h + (size_t)s1 * 32) + t);
        uint2 f2 = __ldg((const uint2*)(h + (size_t)s2 * 32) + t);
        uint2 f3 = __ldg((const uint2*)(h + (size_t)s3 * 32) + t);
        uint2 f4 = __ldg((const uint2*)(h + (size_t)s4 * 32) + t);
        uint2 f5 = __ldg((const uint2*)(h + (size_t)s5 * 32) + t);
        uint2 f6 = __ldg((const uint2*)(h + (size_t)s6 * 32) + t);
        uint2 f7 = __ldg((const uint2*)(h + (size_t)s7 * 32) + t);
        acc.x += bf_lo(f0.x); acc.y += bf_hi(f0.x);
        acc.z += bf_lo(f0.y); acc.w += bf_hi(f0.y);
        acc.x += bf_lo(f1.x); acc.y += bf_hi(f1.x);
        acc.z += bf_lo(f1.y); acc.w += bf_hi(f1.y);
        acc.x += bf_lo(f2.x); acc.y += bf_hi(f2.x);
        acc.z += bf_lo(f2.y); acc.w += bf_hi(f2.y);
        acc.x += bf_lo(f3.x); acc.y += bf_hi(f3.x);
        acc.z += bf_lo(f3.y); acc.w += bf_hi(f3.y);
        acc.x += bf_lo(f4.x); acc.y += bf_hi(f4.x);
        acc.z += bf_lo(f4.y); acc.w += bf_hi(f4.y);
        acc.x += bf_lo(f5.x); acc.y += bf_hi(f5.x);
        acc.z += bf_lo(f5.y); acc.w += bf_hi(f5.y);
        acc.x += bf_lo(f6.x); acc.y += bf_hi(f6.x);
        acc.z += bf_lo(f6.y); acc.w += bf_hi(f6.y);
        acc.x += bf_lo(f7.x); acc.y += bf_hi(f7.x);
        acc.z += bf_lo(f7.y); acc.w += bf_hi(f7.y);
    }
    for (; k < e1; k += 2) {
        int s = __ldg(&g_csr[k]);
        uint2 f = __ldg((const uint2*)(h + (size_t)s * 32) + t);
        acc.x += bf_lo(f.x); acc.y += bf_hi(f.x);
        acc.z += bf_lo(f.y); acc.w += bf_hi(f.y);
    }
    // dinv[dst], then combine the two halves
    acc.x *= dv; acc.y *= dv; acc.z *= dv; acc.w *= dv;
    acc.x += __shfl_xor_sync(0xffffffffu, acc.x, 16);
    acc.y += __shfl_xor_sync(0xffffffffu, acc.y, 16);
    acc.z += __shfl_xor_sync(0xffffffffu, acc.z, 16);
    acc.w += __shfl_xor_sync(0xffffffffu, acc.w, 16);
    if (sub == 0) {
        uint2 st;
        st.x = bf2_pack(acc.x, acc.y);
        st.y = bf2_pack(acc.z, acc.w);
        ((uint2*)(g_aggu + (size_t)w * 32))[t] = st;
    }
}

// ---------------- matmul 64x64 + bias + relu: g_aggu (bf16) -> bf16 buffer ---
// SCALE=1: multiply rows by dinv[row] on output (feeds another aggregation).
template <int DST, int SCALE>
__global__ void k_mm64(const float* __restrict__ Wm, const float* __restrict__ bv) {
    unsigned* __restrict__ out = (DST == 0) ? g_ha : g_hb;
    __shared__ float4 sIn[64 * 16];
    __shared__ float sDv[64];
    int tid = threadIdx.x;           // 256
    int row0 = blockIdx.x * 64;
    int col = tid & 63;
    float wreg[64];
#pragma unroll
    for (int k = 0; k < 64; k++) wreg[k] = __ldg(&Wm[k * 64 + col]);
    float bias = __ldg(&bv[col]);
    int nrows = min(64, N_NODES - row0);
    for (int idx = tid; idx < nrows * 16; idx += 256) {
        uint2 v = __ldg((const uint2*)(g_aggu + (size_t)row0 * 32) + idx);
        sIn[idx] = make_float4(bf_lo(v.x), bf_hi(v.x), bf_lo(v.y), bf_hi(v.y));
    }
    if (SCALE && tid < nrows) sDv[tid] = g_dinv[row0 + tid];
    __syncthreads();
    int rg = tid >> 6;
    for (int r = rg; r < nrows; r += 4) {
        float acc = bias;
#pragma unroll
        for (int k4 = 0; k4 < 16; k4++) {
            float4 v = sIn[r * 16 + k4];
            acc = fmaf(v.x, wreg[4 * k4 + 0], acc);
            acc = fmaf(v.y, wreg[4 * k4 + 1], acc);
            acc = fmaf(v.z, wreg[4 * k4 + 2], acc);
            acc = fmaf(v.w, wreg[4 * k4 + 3], acc);
        }
        acc = fmaxf(acc, 0.f);
        if (SCALE) acc *= sDv[r];
        // pair with neighbor column and store one bf16x2 per even thread
        float nxt = __shfl_down_sync(0xffffffffu, acc, 1);
        if ((tid & 1) == 0)
            out[(size_t)(row0 + r) * 32 + (col >> 1)] = bf2_pack(acc, nxt);
    }
}

// ---------------- fused mean pool + MLP head (last block does the head) ------
__global__ void k_pool_head(const int* __restrict__ batch,
                            const float* __restrict__ Wf1, const float* __restrict__ bf1,
                            const float* __restrict__ Wf2, const float* __restrict__ bf2,
                            float* __restrict__ out) {
    int g = blockIdx.x;
    int lo = 0, hi = N_NODES;
    while (lo < hi) { int mid = (lo + hi) >> 1; if (__ldg(&batch[mid]) < g) lo = mid + 1; else hi = mid; }
    int start = lo;
    lo = start; hi = N_NODES;
    while (lo < hi) { int mid = (lo + hi) >> 1; if (__ldg(&batch[mid]) < g + 1) lo = mid + 1; else hi = mid; }
    int end = lo;

    __shared__ float2 sp[8][32];
    int cp = threadIdx.x & 31, rg = threadIdx.x >> 5;
    float2 acc = make_float2(0.f, 0.f);
    for (int r = start + rg; r < end; r += 8) {
        unsigned u = __ldg(&g_ha[(size_t)r * 32 + cp]);
        acc.x += bf_lo(u); acc.y += bf_hi(u);
    }
    sp[rg][cp] = acc;
    __syncthreads();
    if (rg == 0) {
        float2 t = sp[0][cp];
#pragma unroll
        for (int i = 1; i < 8; i++) { t.x += sp[i][cp].x; t.y += sp[i][cp].y; }
        float cnt = (float)(end - start);
        if (cnt < 1.f) cnt = 1.f;
        ((float2*)g_pool)[g * 32 + cp] = make_float2(t.x / cnt, t.y / cnt);
    }

    // last block to finish runs the head
    __shared__ int s_last;
    __threadfence();
    __syncthreads();
    if (threadIdx.x == 0) s_last = (atomicAdd(&g_done, 1) == N_GRAPHS - 1);
    __syncthreads();
    if (!s_last) return;
    __threadfence();

    int gg = threadIdx.x;
    if (gg >= N_GRAPHS) return;
    float p[64];
#pragma unroll
    for (int k = 0; k < 64; k++) p[k] = g_pool[gg * 64 + k];
    float o = __ldg(&bf2[0]);
#pragma unroll 4
    for (int j = 0; j < 32; j++) {
        float hj = __ldg(&bf1[j]);
#pragma unroll
        for (int k = 0; k < 64; k++) hj = fmaf(p[k], __ldg(&Wf1[k * 32 + j]), hj);
        o = fmaf(fmaxf(hj, 0.f), __ldg(&Wf2[j]), o);
    }
    out[gg] = o;
}

// ---------------- launch ----------------
extern "C" void kernel_launch(void* const* d_in, const int* in_sizes, int n_in,
                              void* d_out, int out_size) {
    const float* x   = (const float*)d_in[0];
    const int*   ei  = (const int*)d_in[1];
    const int4*  src4 = (const int4*)ei;
    const int4*  dst4 = (const int4*)(ei + N_EDGES);
    const int*   batch = (const int*)d_in[3];
    const float* W1 = (const float*)d_in[4];  const float* b1 = (const float*)d_in[5];
    const float* W2 = (const float*)d_in[6];  const float* b2 = (const float*)d_in[7];
    const float* W3 = (const float*)d_in[8];  const float* b3 = (const float*)d_in[9];
    const float* Wf1 = (const float*)d_in[10]; const float* bf1 = (const float*)d_in[11];
    const float* Wf2 = (const float*)d_in[12]; const float* bf2 = (const float*)d_in[13];
    float* out = (float*)d_out;

    const int nb_scan = (N_NODES + 1023) / 1024;       // 98
    const int eb4 = (N_EDGES / 4) / 256;               // 3125
    const int wb = (N_NODES * 32 + 255) / 256;         // one warp per node: 12500
    const int mb = (N_NODES + 63) / 64;                // 1563

    k_zero_cnt<<<(N_NODES + 255) / 256, 256>>>();
    k_hist<<<eb4, 256>>>(dst4);
    k_scan_blocks<<<nb_scan, 1024>>>();
    k_scan_add<<<nb_scan, 1024>>>(x);
    k_fill<<<eb4, 256>>>(src4, dst4);

    k_agg16_mm1<<<wb, 256>>>(W1, b1);          // layer 1 fused -> ha (scaled)
    k_agg64<0><<<wb, 256>>>();                 // gather ha -> aggu
    k_mm64<1, 1><<<mb, 256>>>(W2, b2);         // aggu@W2 -> hb (scaled)
    k_agg64<1><<<wb, 256>>>();                 // gather hb -> aggu
    k_mm64<0, 0><<<mb, 256>>>(W3, b3);         // aggu@W3 -> ha (raw, for pool)

    k_pool_head<<<N_GRAPHS, 256>>>(batch, Wf1, bf1, Wf2, bf2, out);
}

// round 16
// speedup vs baseline: 1.0975x; 1.0740x over previous
#include <cuda_runtime.h>
#include <cuda_bf16.h>

#define N_NODES  100000
#define N_EDGES  3200000
#define N_GRAPHS 128

// ---------------- scratch (static device globals; no runtime alloc) ----------
__device__ int   g_cnt[N_NODES];
__device__ int   g_rowptr[N_NODES];            // after k_fill: END of each row
__device__ int   g_bsums[128];
__device__ float g_dinv[N_NODES];
__device__ int   g_csr[N_EDGES];               // src only (features pre-scaled by dinv)
__device__ __align__(16) unsigned g_xs[N_NODES * 8];    // x*dinv as bf16 pairs
__device__ __align__(16) unsigned g_aggu[N_NODES * 32]; // aggregation output (bf16 pairs)
__device__ __align__(16) unsigned g_ha[N_NODES * 32];   // activations bf16 (L1, scaled)
__device__ __align__(16) unsigned g_hb[N_NODES * 32];   // activations bf16 (L2, scaled)
__device__ __align__(16) float g_pool[N_GRAPHS * 64];   // per-graph col sums (atomic)

// bf16 pair decode: EXACT (bf16 is fp32 with truncated mantissa). 1 instr each.
__device__ __forceinline__ float bf_lo(unsigned v) { return __int_as_float(v << 16); }
__device__ __forceinline__ float bf_hi(unsigned v) { return __int_as_float(v & 0xffff0000u); }
// pack two floats into a bf16 pair (lo = first/even column), single instruction
__device__ __forceinline__ unsigned bf2_pack(float lo, float hi) {
    unsigned r;
    asm("cvt.rn.bf16x2.f32 %0, %1, %2;" : "=r"(r) : "f"(hi), "f"(lo));
    return r;
}
// packed bf16x2 add (HADD2.BF16_V2) — 2 columns per instruction
__device__ __forceinline__ unsigned badd(unsigned a, unsigned b) {
    __nv_bfloat162 r = __hadd2(*(__nv_bfloat162*)&a, *(__nv_bfloat162*)&b);
    return *(unsigned*)&r;
}

// ---------------- zero counters + pool ----------------
__global__ void k_zero_cnt() {
    int i = blockIdx.x * blockDim.x + threadIdx.x;
    if (i < N_NODES) g_cnt[i] = 0;
    if (i < N_GRAPHS * 64) g_pool[i] = 0.f;
}

__global__ void k_hist(const int4* __restrict__ dst4) {
    int i = blockIdx.x * blockDim.x + threadIdx.x;   // N_EDGES/4 threads
    int4 d = __ldg(&dst4[i]);
    atomicAdd(&g_cnt[d.x], 1);
    atomicAdd(&g_cnt[d.y], 1);
    atomicAdd(&g_cnt[d.z], 1);
    atomicAdd(&g_cnt[d.w], 1);
}

// ---------------- exclusive scan over 100k counts (2 kernels) ----------------
__global__ void k_scan_blocks() {
    __shared__ int s[1024];
    int tid = threadIdx.x;
    int i = blockIdx.x * 1024 + tid;
    int v = (i < N_NODES) ? g_cnt[i] : 0;
    s[tid] = v;
    __syncthreads();
    for (int off = 1; off < 1024; off <<= 1) {
        int t = (tid >= off) ? s[tid - off] : 0;
        __syncthreads();
        s[tid] += t;
        __syncthreads();
    }
    if (i < N_NODES) g_rowptr[i] = s[tid] - v;   // exclusive within block
    if (tid == 1023) g_bsums[blockIdx.x] = s[1023];
}

// scan finish + dinv + pre-scaled bf16 x (fused)
__global__ void k_scan_add(const float* __restrict__ x) {
    __shared__ int s_pre;
    int tid = threadIdx.x;
    if (tid < 32) {
        int acc = 0;
        for (int b = tid; b < blockIdx.x; b += 32) acc += g_bsums[b];
        for (int off = 16; off > 0; off >>= 1) acc += __shfl_xor_sync(0xffffffffu, acc, off);
        if (tid == 0) s_pre = acc;
    }
    __syncthreads();
    int i = blockIdx.x * 1024 + tid;
    if (i < N_NODES) {
        g_rowptr[i] += s_pre;
        float dv = rsqrtf((float)(g_cnt[i] + 1));   // +1 self loop
        g_dinv[i] = dv;
        const float4* xr = (const float4*)(x + (size_t)i * 16);
        uint4* xo = (uint4*)(g_xs + (size_t)i * 8);
#pragma unroll
        for (int c = 0; c < 2; c++) {
            float4 v0 = __ldg(&xr[2 * c]);
            float4 v1 = __ldg(&xr[2 * c + 1]);
            uint4 u;
            u.x = bf2_pack(v0.x * dv, v0.y * dv);
            u.y = bf2_pack(v0.z * dv, v0.w * dv);
            u.z = bf2_pack(v1.x * dv, v1.y * dv);
            u.w = bf2_pack(v1.z * dv, v1.w * dv);
            xo[c] = u;
        }
    }
}

// ---------------- CSR fill: rowptr itself is the cursor (becomes row END) ----
__global__ void k_fill(const int4* __restrict__ src4, const int4* __restrict__ dst4) {
    int i = blockIdx.x * blockDim.x + threadIdx.x;   // N_EDGES/4 threads
    int4 s = __ldg(&src4[i]);
    int4 d = __ldg(&dst4[i]);
    g_csr[atomicAdd(&g_rowptr[d.x], 1)] = s.x;
    g_csr[atomicAdd(&g_rowptr[d.y], 1)] = s.y;
    g_csr[atomicAdd(&g_rowptr[d.z], 1)] = s.z;
    g_csr[atomicAdd(&g_rowptr[d.w], 1)] = s.w;
}

// ---------------- layer 1 fused: agg(xs,16) then @W1[16,64]+b1, relu --------
// warp per node; 4 subs of 8 lanes, sub handles every-4th edge; lane = col pair.
// writes g_ha PRE-SCALED by dinv[w] for layer-2 consumption.
__global__ void k_agg16_mm1(const float* __restrict__ W1, const float* __restrict__ b1) {
    __shared__ float2 sW[16 * 32];
    __shared__ float2 sB[32];
    int tid = threadIdx.x;
    for (int idx = tid; idx < 16 * 32; idx += 256) sW[idx] = __ldg((const float2*)W1 + idx);
    if (tid < 32) sB[tid] = __ldg((const float2*)b1 + tid);
    __syncthreads();

    int w = (blockIdx.x * 256 + tid) >> 5;
    if (w >= N_NODES) return;
    int lane = tid & 31;
    int sub = lane >> 3, c2 = lane & 7;     // c2 covers cols {2c2, 2c2+1}
    int e1 = __ldg(&g_rowptr[w]);
    int e0 = e1 - __ldg(&g_cnt[w]);
    float2 a = make_float2(0.f, 0.f);
    float dv = g_dinv[w];
    if (sub == 0) {                          // self loop (xs already dinv-scaled)
        unsigned u = __ldg(&g_xs[(size_t)w * 8 + c2]);
        a.x = bf_lo(u); a.y = bf_hi(u);
    }
    int k = e0 + sub;
    for (; k + 12 < e1; k += 16) {           // 4 edges per sub in flight (16/warp)
        int s0 = __ldg(&g_csr[k]);
        int s1 = __ldg(&g_csr[k + 4]);
        int s2 = __ldg(&g_csr[k + 8]);
        int s3 = __ldg(&g_csr[k + 12]);
        unsigned u0 = __ldg(&g_xs[(size_t)s0 * 8 + c2]);
        unsigned u1 = __ldg(&g_xs[(size_t)s1 * 8 + c2]);
        unsigned u2 = __ldg(&g_xs[(size_t)s2 * 8 + c2]);
        unsigned u3 = __ldg(&g_xs[(size_t)s3 * 8 + c2]);
        unsigned t = badd(badd(u0, u1), badd(u2, u3));   // bf16 tree (depth 2)
        a.x += bf_lo(t); a.y += bf_hi(t);
    }
    for (; k < e1; k += 4) {
        unsigned u = __ldg(&g_xs[(size_t)__ldg(&g_csr[k]) * 8 + c2]);
        a.x += bf_lo(u); a.y += bf_hi(u);
    }
    a.x *= dv; a.y *= dv;                    // dinv[dst]
    // combine 4 subs
    a.x += __shfl_xor_sync(0xffffffffu, a.x, 8);
    a.y += __shfl_xor_sync(0xffffffffu, a.y, 8);
    a.x += __shfl_xor_sync(0xffffffffu, a.x, 16);
    a.y += __shfl_xor_sync(0xffffffffu, a.y, 16);
    // lane j (j<8) holds agg cols {2j, 2j+1}; replicated in all lanes

    // mm 16 -> 64: lane computes cols {2*lane, 2*lane+1}
    float2 acc = sB[lane];
#pragma unroll
    for (int kk = 0; kk < 16; kk++) {
        float ak = __shfl_sync(0xffffffffu, (kk & 1) ? a.y : a.x, kk >> 1);
        float2 wv = sW[kk * 32 + lane];
        acc.x = fmaf(ak, wv.x, acc.x);
        acc.y = fmaf(ak, wv.y, acc.y);
    }
    // pre-scale by dinv[w] for next layer's aggregation
    g_ha[(size_t)w * 32 + lane] = bf2_pack(fmaxf(acc.x, 0.f) * dv, fmaxf(acc.y, 0.f) * dv);
}

// ---------------- 64-wide aggregation over pre-scaled bf16 -> g_aggu ---------
// 2 subs x 16 lanes x uint2; 8 edges per sub in flight; bf16 tree accumulation.
template <int SRC>
__global__ void k_agg64() {
    const unsigned* __restrict__ h = (SRC == 0) ? g_ha : g_hb;
    int w = (blockIdx.x * 256 + threadIdx.x) >> 5;
    if (w >= N_NODES) return;
    int lane = threadIdx.x & 31;
    int sub = lane >> 4, t = lane & 15;      // t covers cols {4t..4t+3}
    int e1 = __ldg(&g_rowptr[w]);
    int e0 = e1 - __ldg(&g_cnt[w]);
    float dv = g_dinv[w];

    float4 acc = make_float4(0.f, 0.f, 0.f, 0.f);
    if (sub == 0) {                          // self loop
        uint2 sv = __ldg((const uint2*)(h + (size_t)w * 32) + t);
        acc.x = bf_lo(sv.x); acc.y = bf_hi(sv.x);
        acc.z = bf_lo(sv.y); acc.w = bf_hi(sv.y);
    }

    int k = e0 + sub;
    for (; k + 14 < e1; k += 16) {           // 8 edges per sub in flight
        int s0 = __ldg(&g_csr[k]);
        int s1 = __ldg(&g_csr[k + 2]);
        int s2 = __ldg(&g_csr[k + 4]);
        int s3 = __ldg(&g_csr[k + 6]);
        int s4 = __ldg(&g_csr[k + 8]);
        int s5 = __ldg(&g_csr[k + 10]);
        int s6 = __ldg(&g_csr[k + 12]);
        int s7 = __ldg(&g_csr[k + 14]);
        uint2 f0 = __ldg((const uint2*)(h + (size_t)s0 * 32) + t);
        uint2 f1 = __ldg((const uint2*)(h + (size_t)s1 * 32) + t);
        uint2 f2 = __ldg((const uint2*)(h + (size_t)s2 * 32) + t);
        uint2 f3 = __ldg((const uint2*)(h + (size_t)s3 * 32) + t);
        uint2 f4 = __ldg((const uint2*)(h + (size_t)s4 * 32) + t);
        uint2 f5 = __ldg((const uint2*)(h + (size_t)s5 * 32) + t);
        uint2 f6 = __ldg((const uint2*)(h + (size_t)s6 * 32) + t);
        uint2 f7 = __ldg((const uint2*)(h + (size_t)s7 * 32) + t);
        // bf16 tree (depth 3) per packed column pair, then one fp32 add
        unsigned tx = badd(badd(badd(f0.x, f1.x), badd(f2.x, f3.x)),
                           badd(badd(f4.x, f5.x), badd(f6.x, f7.x)));
        unsigned ty = badd(badd(badd(f0.y, f1.y), badd(f2.y, f3.y)),
                           badd(badd(f4.y, f5.y), badd(f6.y, f7.y)));
        acc.x += bf_lo(tx); acc.y += bf_hi(tx);
        acc.z += bf_lo(ty); acc.w += bf_hi(ty);
    }
    for (; k < e1; k += 2) {
        int s = __ldg(&g_csr[k]);
        uint2 f = __ldg((const uint2*)(h + (size_t)s * 32) + t);
        acc.x += bf_lo(f.x); acc.y += bf_hi(f.x);
        acc.z += bf_lo(f.y); acc.w += bf_hi(f.y);
    }
    // dinv[dst], then combine the two halves
    acc.x *= dv; acc.y *= dv; acc.z *= dv; acc.w *= dv;
    acc.x += __shfl_xor_sync(0xffffffffu, acc.x, 16);
    acc.y += __shfl_xor_sync(0xffffffffu, acc.y, 16);
    acc.z += __shfl_xor_sync(0xffffffffu, acc.z, 16);
    acc.w += __shfl_xor_sync(0xffffffffu, acc.w, 16);
    if (sub == 0) {
        uint2 st;
        st.x = bf2_pack(acc.x, acc.y);
        st.y = bf2_pack(acc.z, acc.w);
        ((uint2*)(g_aggu + (size_t)w * 32))[t] = st;
    }
}

// ---------------- matmul 64x64 + bias + relu ------------------------------
// SCALE=1: multiply rows by dinv[row] (output feeds another aggregation).
// POOL=1: don't write activations; segment-accumulate per-graph sums into g_pool.
template <int DST, int SCALE, int POOL>
__global__ void k_mm64(const float* __restrict__ Wm, const float* __restrict__ bv,
                       const int* __restrict__ batch) {
    unsigned* __restrict__ out = (DST == 0) ? g_ha : g_hb;
    __shared__ float4 sIn[64 * 16];
    __shared__ float sDv[64];
    __shared__ int sBatch[64];
    int tid = threadIdx.x;           // 256
    int row0 = blockIdx.x * 64;
    int col = tid & 63;
    float wreg[64];
#pragma unroll
    for (int k = 0; k < 64; k++) wreg[k] = __ldg(&Wm[k * 64 + col]);
    float bias = __ldg(&bv[col]);
    int nrows = min(64, N_NODES - row0);
    for (int idx = tid; idx < nrows * 16; idx += 256) {
        uint2 v = __ldg((const uint2*)(g_aggu + (size_t)row0 * 32) + idx);
        sIn[idx] = make_float4(bf_lo(v.x), bf_hi(v.x), bf_lo(v.y), bf_hi(v.y));
    }
    if (SCALE && tid < nrows) sDv[tid] = g_dinv[row0 + tid];
    if (POOL && tid < nrows) sBatch[tid] = __ldg(&batch[row0 + tid]);
    __syncthreads();
    int rg = tid >> 6;
    int curg = -1;
    float psum = 0.f;
    for (int r = rg; r < nrows; r += 4) {
        float acc = bias;
#pragma unroll
        for (int k4 = 0; k4 < 16; k4++) {
            float4 v = sIn[r * 16 + k4];
            acc = fmaf(v.x, wreg[4 * k4 + 0], acc);
            acc = fmaf(v.y, wreg[4 * k4 + 1], acc);
            acc = fmaf(v.z, wreg[4 * k4 + 2], acc);
            acc = fmaf(v.w, wreg[4 * k4 + 3], acc);
        }
        acc = fmaxf(acc, 0.f);
        if (POOL) {
            int bg = sBatch[r];              // nondecreasing over this thread's rows
            if (bg != curg) {
                if (curg >= 0) atomicAdd(&g_pool[curg * 64 + col], psum);
                psum = 0.f;
                curg = bg;
            }
            psum += acc;
        } else {
            if (SCALE) acc *= sDv[r];
            // pair with neighbor column and store one bf16x2 per even thread
            float nxt = __shfl_down_sync(0xffffffffu, acc, 1);
            if ((tid & 1) == 0)
                out[(size_t)(row0 + r) * 32 + (col >> 1)] = bf2_pack(acc, nxt);
        }
    }
    if (POOL && curg >= 0) atomicAdd(&g_pool[curg * 64 + col], psum);
}

// ---------------- MLP head (reads g_pool sums; divides by graph size) --------
__global__ void k_head(const int* __restrict__ batch,
                       const float* __restrict__ Wf1, const float* __restrict__ bf1,
                       const float* __restrict__ Wf2, const float* __restrict__ bf2,
                       float* __restrict__ out) {
    int g = threadIdx.x;
    if (g >= N_GRAPHS) return;
    int lo = 0, hi = N_NODES;
    while (lo < hi) { int mid = (lo + hi) >> 1; if (__ldg(&batch[mid]) < g) lo = mid + 1; else hi = mid; }
    int start = lo;
    lo = start; hi = N_NODES;
    while (lo < hi) { int mid = (lo + hi) >> 1; if (__ldg(&batch[mid]) < g + 1) lo = mid + 1; else hi = mid; }
    float cnt = (float)(lo - start);
    float inv = 1.f / fmaxf(cnt, 1.f);

    float p[64];
#pragma unroll
    for (int k = 0; k < 64; k++) p[k] = g_pool[g * 64 + k] * inv;
    float o = __ldg(&bf2[0]);
#pragma unroll 4
    for (int j = 0; j < 32; j++) {
        float hj = __ldg(&bf1[j]);
#pragma unroll
        for (int k = 0; k < 64; k++) hj = fmaf(p[k], __ldg(&Wf1[k * 32 + j]), hj);
        o = fmaf(fmaxf(hj, 0.f), __ldg(&Wf2[j]), o);
    }
    out[g] = o;
}

// ---------------- launch ----------------
extern "C" void kernel_launch(void* const* d_in, const int* in_sizes, int n_in,
                              void* d_out, int out_size) {
    const float* x   = (const float*)d_in[0];
    const int*   ei  = (const int*)d_in[1];
    const int4*  src4 = (const int4*)ei;
    const int4*  dst4 = (const int4*)(ei + N_EDGES);
    const int*   batch = (const int*)d_in[3];
    const float* W1 = (const float*)d_in[4];  const float* b1 = (const float*)d_in[5];
    const float* W2 = (const float*)d_in[6];  const float* b2 = (const float*)d_in[7];
    const float* W3 = (const float*)d_in[8];  const float* b3 = (const float*)d_in[9];
    const float* Wf1 = (const float*)d_in[10]; const float* bf1 = (const float*)d_in[11];
    const float* Wf2 = (const float*)d_in[12]; const float* bf2 = (const float*)d_in[13];
    float* out = (float*)d_out;

    const int nb_scan = (N_NODES + 1023) / 1024;       // 98
    const int eb4 = (N_EDGES / 4) / 256;               // 3125
    const int wb = (N_NODES * 32 + 255) / 256;         // one warp per node: 12500
    const int mb = (N_NODES + 63) / 64;                // 1563

    k_zero_cnt<<<(N_NODES + 255) / 256, 256>>>();
    k_hist<<<eb4, 256>>>(dst4);
    k_scan_blocks<<<nb_scan, 1024>>>();
    k_scan_add<<<nb_scan, 1024>>>(x);
    k_fill<<<eb4, 256>>>(src4, dst4);

    k_agg16_mm1<<<wb, 256>>>(W1, b1);               // layer 1 fused -> ha (scaled)
    k_agg64<0><<<wb, 256>>>();                      // gather ha -> aggu
    k_mm64<1, 1, 0><<<mb, 256>>>(W2, b2, batch);    // aggu@W2 -> hb (scaled)
    k_agg64<1><<<wb, 256>>>();                      // gather hb -> aggu
    k_mm64<0, 0, 1><<<mb, 256>>>(W3, b3, batch);    // aggu@W3 -> pool sums (fp32)

    k_head<<<1, 128>>>(batch, Wf1, bf1, Wf2, bf2, out);
}